// round 2
// baseline (speedup 1.0000x reference)
#include <cuda_runtime.h>
#include <math.h>

#define C 10
#define NSTATS 31          // 10 sum_p, 10 sum_p2, 10 sum_x, 1 sum_logS
#define NBLOCKS 1184
#define NTHREADS 256

// Per-block partial sums (written fully each launch -> deterministic, no atomics)
__device__ float g_partials[NBLOCKS * 32];

// ---------------------------------------------------------------------------
// Kernel 1: stream x[n,10], accumulate sufficient statistics.
// Each thread handles PAIRS of rows: 2 rows = 20 floats = 80 bytes = 5 float4
// (16B-aligned since 80 % 16 == 0), so loads are LDG.128.
// ---------------------------------------------------------------------------
__global__ void __launch_bounds__(NTHREADS)
stats_kernel(const float* __restrict__ x, int n)
{
    float sp[C];   // sum p
    float sp2[C];  // sum p^2
    float sx[C];   // sum x
    float slog = 0.0f;  // sum log S
#pragma unroll
    for (int j = 0; j < C; j++) { sp[j] = 0.0f; sp2[j] = 0.0f; sx[j] = 0.0f; }

    const int npairs = n >> 1;
    const int stride = gridDim.x * blockDim.x;

    for (int pair = blockIdx.x * blockDim.x + threadIdx.x; pair < npairs; pair += stride) {
        const float4* base = reinterpret_cast<const float4*>(x) + (size_t)pair * 5;
        float v[20];
        float4 t0 = __ldg(base + 0);
        float4 t1 = __ldg(base + 1);
        float4 t2 = __ldg(base + 2);
        float4 t3 = __ldg(base + 3);
        float4 t4 = __ldg(base + 4);
        v[0]=t0.x; v[1]=t0.y; v[2]=t0.z; v[3]=t0.w;
        v[4]=t1.x; v[5]=t1.y; v[6]=t1.z; v[7]=t1.w;
        v[8]=t2.x; v[9]=t2.y; v[10]=t2.z; v[11]=t2.w;
        v[12]=t3.x; v[13]=t3.y; v[14]=t3.z; v[15]=t3.w;
        v[16]=t4.x; v[17]=t4.y; v[18]=t4.z; v[19]=t4.w;

#pragma unroll
        for (int r = 0; r < 2; r++) {
            const float* xr = v + r * C;
            float e[C];
            float S = 0.0f;
#pragma unroll
            for (int j = 0; j < C; j++) { e[j] = __expf(xr[j]); S += e[j]; }
            float rS = __fdividef(1.0f, S);
            slog += __logf(S);
#pragma unroll
            for (int j = 0; j < C; j++) {
                float p = e[j] * rS;
                sp[j]  += p;
                sp2[j]  = fmaf(p, p, sp2[j]);
                sx[j]  += xr[j];
            }
        }
    }

    // Tail row if n is odd (handled by one thread)
    if ((n & 1) && blockIdx.x == 0 && threadIdx.x == 0) {
        const float* xr = x + (size_t)(n - 1) * C;
        float e[C];
        float S = 0.0f;
#pragma unroll
        for (int j = 0; j < C; j++) { e[j] = __expf(xr[j]); S += e[j]; }
        float rS = __fdividef(1.0f, S);
        slog += __logf(S);
#pragma unroll
        for (int j = 0; j < C; j++) {
            float p = e[j] * rS;
            sp[j]  += p;
            sp2[j]  = fmaf(p, p, sp2[j]);
            sx[j]  += xr[j];
        }
    }

    // Warp reduction of 31 values
#pragma unroll
    for (int off = 16; off > 0; off >>= 1) {
#pragma unroll
        for (int j = 0; j < C; j++) {
            sp[j]  += __shfl_down_sync(0xffffffffu, sp[j],  off);
            sp2[j] += __shfl_down_sync(0xffffffffu, sp2[j], off);
            sx[j]  += __shfl_down_sync(0xffffffffu, sx[j],  off);
        }
        slog += __shfl_down_sync(0xffffffffu, slog, off);
    }

    __shared__ float sm[NTHREADS / 32][NSTATS];
    const int warp = threadIdx.x >> 5;
    const int lane = threadIdx.x & 31;
    if (lane == 0) {
#pragma unroll
        for (int j = 0; j < C; j++) {
            sm[warp][j]        = sp[j];
            sm[warp][C + j]    = sp2[j];
            sm[warp][2*C + j]  = sx[j];
        }
        sm[warp][30] = slog;
    }
    __syncthreads();

    if (threadIdx.x < NSTATS) {
        float s = 0.0f;
#pragma unroll
        for (int w = 0; w < NTHREADS / 32; w++) s += sm[w][threadIdx.x];
        g_partials[(size_t)blockIdx.x * 32 + threadIdx.x] = s;
    }
}

// ---------------------------------------------------------------------------
// Kernel 2: reduce partials (double), compute moment init + Newton iterations.
// ---------------------------------------------------------------------------
__device__ double digamma_d(double x)
{
    double r = 0.0;
    while (x < 6.0) { r -= 1.0 / x; x += 1.0; }
    double f = 1.0 / (x * x);
    double series = f * (1.0/12.0 - f * (1.0/120.0 - f * (1.0/252.0 - f * (1.0/240.0 - f * (1.0/132.0)))));
    return r + log(x) - 0.5 / x - series;
}

__device__ double trigamma_d(double x)
{
    double r = 0.0;
    while (x < 6.0) { r += 1.0 / (x * x); x += 1.0; }
    double f = 1.0 / (x * x);
    double s = (1.0 + 0.5 / x + f * (1.0/6.0 - f * (1.0/30.0 - f * (1.0/42.0 - f * (1.0/30.0))))) / x;
    return r + s;
}

__global__ void finalize_kernel(float* __restrict__ out, int n)
{
    __shared__ double red[8][32];
    __shared__ double stat[32];
    const int t    = threadIdx.x;   // 256 threads
    const int comp = t & 31;
    const int row  = t >> 5;

    double acc = 0.0;
    for (int b = row; b < NBLOCKS; b += 8)
        acc += (double)g_partials[(size_t)b * 32 + comp];
    red[row][comp] = acc;
    __syncthreads();

    if (t < 32) {
        double s = 0.0;
#pragma unroll
        for (int w = 0; w < 8; w++) s += red[w][t];
        stat[t] = s;
    }
    __syncthreads();

    if (t == 0) {
        const double nn = (double)n;
        double m1[C], m2[C], lp[C];
        const double slog = stat[30];
        for (int j = 0; j < C; j++) {
            m1[j] = stat[j]       / nn;
            m2[j] = stat[C + j]   / nn;
            lp[j] = (stat[2*C + j] - slog) / nn;   // mean log p_j
        }
        // method-of-moments init
        double ratio_sum = 0.0;
        for (int j = 0; j < C; j++)
            ratio_sum += (m1[j] - m2[j]) / (m2[j] - m1[j] * m1[j]);
        const double cc = ratio_sum / (double)C;
        double a[C];
        for (int j = 0; j < C; j++) a[j] = m1[j] * cc;

        // Newton with rank-1 Hessian inverse; same stopping rule as reference
        double diff = 1e300;
        for (int k = 0; k < 100 && diff >= 1e-3; k++) {
            double sumA = 0.0;
            for (int j = 0; j < C; j++) sumA += a[j];
            const double dgs = digamma_d(sumA);
            const double z   = nn * trigamma_d(sumA);
            double g[C], q[C];
            double num = 0.0, den = 1.0 / z;
            for (int j = 0; j < C; j++) {
                g[j] = (dgs - digamma_d(a[j]) + lp[j]) * nn;
                q[j] = -nn * trigamma_d(a[j]);
                double qi = 1.0 / q[j];
                num += g[j] * qi;
                den += qi;
            }
            const double b = num / den;
            diff = 0.0;
            for (int j = 0; j < C; j++) {
                double an = a[j] - (g[j] - b) / q[j];
                diff += fabs(an - a[j]);
                a[j] = an;
            }
        }
        for (int j = 0; j < C; j++) out[j] = (float)a[j];
    }
}

extern "C" void kernel_launch(void* const* d_in, const int* in_sizes, int n_in,
                              void* d_out, int out_size)
{
    const float* x = (const float*)d_in[0];
    const int n = in_sizes[0] / C;      // number of rows
    float* out = (float*)d_out;

    stats_kernel<<<NBLOCKS, NTHREADS>>>(x, n);
    finalize_kernel<<<1, 256>>>(out, n);
}

// round 5
// speedup vs baseline: 8.1317x; 8.1317x over previous
#include <cuda_runtime.h>
#include <math.h>

#define C 10
#define NSTATS 31          // 10 sum_p, 10 sum_p2, 10 sum_x, 1 sum_logS
#define NBLOCKS 1184
#define NTHREADS 256

// Per-block partial sums (written fully each launch -> deterministic, no atomics)
__device__ float g_partials[NBLOCKS * 32];

// ---------------------------------------------------------------------------
// Kernel 1: stream x[n,10], accumulate sufficient statistics.
// Each thread handles PAIRS of rows: 2 rows = 20 floats = 80 bytes = 5 float4
// (16B-aligned since 80 % 16 == 0), so loads are LDG.128.
// ---------------------------------------------------------------------------
__global__ void __launch_bounds__(NTHREADS)
stats_kernel(const float* __restrict__ x, int n)
{
    float sp[C];   // sum p
    float sp2[C];  // sum p^2
    float sx[C];   // sum x
    float slog = 0.0f;  // sum log S
#pragma unroll
    for (int j = 0; j < C; j++) { sp[j] = 0.0f; sp2[j] = 0.0f; sx[j] = 0.0f; }

    const int npairs = n >> 1;
    const int stride = gridDim.x * blockDim.x;

    for (int pair = blockIdx.x * blockDim.x + threadIdx.x; pair < npairs; pair += stride) {
        const float4* base = reinterpret_cast<const float4*>(x) + (size_t)pair * 5;
        float v[20];
        float4 t0 = __ldg(base + 0);
        float4 t1 = __ldg(base + 1);
        float4 t2 = __ldg(base + 2);
        float4 t3 = __ldg(base + 3);
        float4 t4 = __ldg(base + 4);
        v[0]=t0.x; v[1]=t0.y; v[2]=t0.z; v[3]=t0.w;
        v[4]=t1.x; v[5]=t1.y; v[6]=t1.z; v[7]=t1.w;
        v[8]=t2.x; v[9]=t2.y; v[10]=t2.z; v[11]=t2.w;
        v[12]=t3.x; v[13]=t3.y; v[14]=t3.z; v[15]=t3.w;
        v[16]=t4.x; v[17]=t4.y; v[18]=t4.z; v[19]=t4.w;

#pragma unroll
        for (int r = 0; r < 2; r++) {
            const float* xr = v + r * C;
            float e[C];
            float S = 0.0f;
#pragma unroll
            for (int j = 0; j < C; j++) { e[j] = __expf(xr[j]); S += e[j]; }
            float rS = __fdividef(1.0f, S);
            slog += __logf(S);
#pragma unroll
            for (int j = 0; j < C; j++) {
                float p = e[j] * rS;
                sp[j]  += p;
                sp2[j]  = fmaf(p, p, sp2[j]);
                sx[j]  += xr[j];
            }
        }
    }

    // Tail row if n is odd (handled by one thread)
    if ((n & 1) && blockIdx.x == 0 && threadIdx.x == 0) {
        const float* xr = x + (size_t)(n - 1) * C;
        float e[C];
        float S = 0.0f;
#pragma unroll
        for (int j = 0; j < C; j++) { e[j] = __expf(xr[j]); S += e[j]; }
        float rS = __fdividef(1.0f, S);
        slog += __logf(S);
#pragma unroll
        for (int j = 0; j < C; j++) {
            float p = e[j] * rS;
            sp[j]  += p;
            sp2[j]  = fmaf(p, p, sp2[j]);
            sx[j]  += xr[j];
        }
    }

    // Warp reduction of 31 values
#pragma unroll
    for (int off = 16; off > 0; off >>= 1) {
#pragma unroll
        for (int j = 0; j < C; j++) {
            sp[j]  += __shfl_down_sync(0xffffffffu, sp[j],  off);
            sp2[j] += __shfl_down_sync(0xffffffffu, sp2[j], off);
            sx[j]  += __shfl_down_sync(0xffffffffu, sx[j],  off);
        }
        slog += __shfl_down_sync(0xffffffffu, slog, off);
    }

    __shared__ float sm[NTHREADS / 32][NSTATS];
    const int warp = threadIdx.x >> 5;
    const int lane = threadIdx.x & 31;
    if (lane == 0) {
#pragma unroll
        for (int j = 0; j < C; j++) {
            sm[warp][j]        = sp[j];
            sm[warp][C + j]    = sp2[j];
            sm[warp][2*C + j]  = sx[j];
        }
        sm[warp][30] = slog;
    }
    __syncthreads();

    if (threadIdx.x < NSTATS) {
        float s = 0.0f;
#pragma unroll
        for (int w = 0; w < NTHREADS / 32; w++) s += sm[w][threadIdx.x];
        g_partials[(size_t)blockIdx.x * 32 + threadIdx.x] = s;
    }
}

// ---------------------------------------------------------------------------
// Kernel 2: reduce partials (double), then fp32 warp-parallel Newton solve.
// ---------------------------------------------------------------------------
__device__ __forceinline__ float digamma_f(float x)
{
    float r = 0.0f;
    while (x < 6.0f) { r -= __fdividef(1.0f, x); x += 1.0f; }
    float inv = __fdividef(1.0f, x);
    float f = inv * inv;
    float series = f * (1.0f/12.0f - f * (1.0f/120.0f - f * (1.0f/252.0f - f * (1.0f/240.0f - f * (1.0f/132.0f)))));
    return r + __logf(x) - 0.5f * inv - series;
}

__device__ __forceinline__ float trigamma_f(float x)
{
    float r = 0.0f;
    while (x < 6.0f) { float inv = __fdividef(1.0f, x); r = fmaf(inv, inv, r); x += 1.0f; }
    float inv = __fdividef(1.0f, x);
    float f = inv * inv;
    float s = (1.0f + 0.5f * inv + f * (1.0f/6.0f - f * (1.0f/30.0f - f * (1.0f/42.0f - f * (1.0f/30.0f))))) * inv;
    return r + s;
}

__device__ __forceinline__ float wsum(float v)
{
#pragma unroll
    for (int off = 16; off > 0; off >>= 1)
        v += __shfl_xor_sync(0xffffffffu, v, off);
    return v;
}

__global__ void finalize_kernel(float* __restrict__ out, int n)
{
    __shared__ double red[8][32];
    __shared__ double stat[32];
    const int t    = threadIdx.x;   // 256 threads
    const int comp = t & 31;
    const int row  = t >> 5;

    double acc = 0.0;
    for (int b = row; b < NBLOCKS; b += 8)
        acc += (double)g_partials[(size_t)b * 32 + comp];
    red[row][comp] = acc;
    __syncthreads();

    if (t < 32) {
        double s = 0.0;
#pragma unroll
        for (int w = 0; w < 8; w++) s += red[w][t];
        stat[t] = s;
    }
    __syncthreads();

    // --- fp32 warp-parallel Newton solve: lane j owns component j ---
    if (t < 32) {
        const double nn_d = (double)n;
        const float  nn   = (float)n;
        const bool   act  = (t < C);

        float m1 = 0.0f, m2 = 0.0f, lp = 0.0f;
        if (act) {
            m1 = (float)(stat[t] / nn_d);
            m2 = (float)(stat[C + t] / nn_d);
            lp = (float)((stat[2*C + t] - stat[30]) / nn_d);  // mean log p_j
        }

        // method-of-moments init
        float ratio = act ? __fdividef(m1 - m2, m2 - m1 * m1) : 0.0f;
        float cc = wsum(ratio) * (1.0f / (float)C);
        float a = m1 * cc;

        float diff = 1e30f;
        for (int k = 0; k < 100 && diff >= 1e-3f; k++) {
            float sumA = wsum(act ? a : 0.0f);
            float dgs  = digamma_f(sumA);
            float z    = nn * trigamma_f(sumA);

            float g = 0.0f, qi = 0.0f, gq = 0.0f;
            if (act) {
                g  = (dgs - digamma_f(a) + lp) * nn;
                float q = -nn * trigamma_f(a);
                qi = __fdividef(1.0f, q);
                gq = g * qi;
            }
            float num = wsum(gq);
            float den = __fdividef(1.0f, z) + wsum(qi);
            float b   = __fdividef(num, den);

            float an = act ? (a - (g - b) * qi) : 0.0f;
            diff = wsum(act ? fabsf(an - a) : 0.0f);
            a = an;
        }
        if (act) out[t] = a;
    }
}

extern "C" void kernel_launch(void* const* d_in, const int* in_sizes, int n_in,
                              void* d_out, int out_size)
{
    const float* x = (const float*)d_in[0];
    const int n = in_sizes[0] / C;      // number of rows
    float* out = (float*)d_out;

    stats_kernel<<<NBLOCKS, NTHREADS>>>(x, n);
    finalize_kernel<<<1, 256>>>(out, n);
}

// round 8
// speedup vs baseline: 8.5488x; 1.0513x over previous
#include <cuda_runtime.h>
#include <math.h>

#define C 10
#define NSTATS 31          // 10 sum_p, 10 sum_p2, 10 sum_x, 1 sum_logS
#define NBLOCKS 1184
#define NTHREADS 256

// Per-block partial sums (written fully each launch -> deterministic, no atomics)
__device__ float g_partials[NBLOCKS * 32];

// ---------------------------------------------------------------------------
// Kernel 1: stream x[n,10], accumulate sufficient statistics.
// Each thread handles PAIRS of rows: 2 rows = 20 floats = 80 bytes = 5 float4
// (16B-aligned since 80 % 16 == 0), so loads are LDG.128.
// ---------------------------------------------------------------------------
__global__ void __launch_bounds__(NTHREADS)
stats_kernel(const float* __restrict__ x, int n)
{
    float sp[C];   // sum p
    float sp2[C];  // sum p^2
    float sx[C];   // sum x
    float slog = 0.0f;  // sum log S
#pragma unroll
    for (int j = 0; j < C; j++) { sp[j] = 0.0f; sp2[j] = 0.0f; sx[j] = 0.0f; }

    const int npairs = n >> 1;
    const int stride = gridDim.x * blockDim.x;

    for (int pair = blockIdx.x * blockDim.x + threadIdx.x; pair < npairs; pair += stride) {
        const float4* base = reinterpret_cast<const float4*>(x) + (size_t)pair * 5;
        float v[20];
        float4 t0 = __ldg(base + 0);
        float4 t1 = __ldg(base + 1);
        float4 t2 = __ldg(base + 2);
        float4 t3 = __ldg(base + 3);
        float4 t4 = __ldg(base + 4);
        v[0]=t0.x; v[1]=t0.y; v[2]=t0.z; v[3]=t0.w;
        v[4]=t1.x; v[5]=t1.y; v[6]=t1.z; v[7]=t1.w;
        v[8]=t2.x; v[9]=t2.y; v[10]=t2.z; v[11]=t2.w;
        v[12]=t3.x; v[13]=t3.y; v[14]=t3.z; v[15]=t3.w;
        v[16]=t4.x; v[17]=t4.y; v[18]=t4.z; v[19]=t4.w;

#pragma unroll
        for (int r = 0; r < 2; r++) {
            const float* xr = v + r * C;
            float e[C];
            float S = 0.0f;
#pragma unroll
            for (int j = 0; j < C; j++) { e[j] = __expf(xr[j]); S += e[j]; }
            float rS = __fdividef(1.0f, S);
            slog += __logf(S);
#pragma unroll
            for (int j = 0; j < C; j++) {
                float p = e[j] * rS;
                sp[j]  += p;
                sp2[j]  = fmaf(p, p, sp2[j]);
                sx[j]  += xr[j];
            }
        }
    }

    // Tail row if n is odd (handled by one thread)
    if ((n & 1) && blockIdx.x == 0 && threadIdx.x == 0) {
        const float* xr = x + (size_t)(n - 1) * C;
        float e[C];
        float S = 0.0f;
#pragma unroll
        for (int j = 0; j < C; j++) { e[j] = __expf(xr[j]); S += e[j]; }
        float rS = __fdividef(1.0f, S);
        slog += __logf(S);
#pragma unroll
        for (int j = 0; j < C; j++) {
            float p = e[j] * rS;
            sp[j]  += p;
            sp2[j]  = fmaf(p, p, sp2[j]);
            sx[j]  += xr[j];
        }
    }

    // Warp reduction of 31 values
#pragma unroll
    for (int off = 16; off > 0; off >>= 1) {
#pragma unroll
        for (int j = 0; j < C; j++) {
            sp[j]  += __shfl_down_sync(0xffffffffu, sp[j],  off);
            sp2[j] += __shfl_down_sync(0xffffffffu, sp2[j], off);
            sx[j]  += __shfl_down_sync(0xffffffffu, sx[j],  off);
        }
        slog += __shfl_down_sync(0xffffffffu, slog, off);
    }

    __shared__ float sm[NTHREADS / 32][NSTATS];
    const int warp = threadIdx.x >> 5;
    const int lane = threadIdx.x & 31;
    if (lane == 0) {
#pragma unroll
        for (int j = 0; j < C; j++) {
            sm[warp][j]        = sp[j];
            sm[warp][C + j]    = sp2[j];
            sm[warp][2*C + j]  = sx[j];
        }
        sm[warp][30] = slog;
    }
    __syncthreads();

    if (threadIdx.x < NSTATS) {
        float s = 0.0f;
#pragma unroll
        for (int w = 0; w < NTHREADS / 32; w++) s += sm[w][threadIdx.x];
        g_partials[(size_t)blockIdx.x * 32 + threadIdx.x] = s;
    }
}

// ---------------------------------------------------------------------------
// Fused digamma + trigamma, branch-free 6-step recurrence (valid for x > 0:
// after 6 predicated increments x >= 6, asymptotic series applies).
// ---------------------------------------------------------------------------
__device__ __forceinline__ void psi01(float x, float& d0, float& d1)
{
    float r0 = 0.0f, r1 = 0.0f;
#pragma unroll
    for (int i = 0; i < 6; i++) {
        float inv = __fdividef(1.0f, x);
        bool small = (x < 6.0f);
        r0 = small ? (r0 - inv) : r0;
        r1 = small ? fmaf(inv, inv, r1) : r1;
        x  = small ? (x + 1.0f) : x;
    }
    float inv = __fdividef(1.0f, x);
    float f = inv * inv;
    float s0 = f * (1.0f/12.0f - f * (1.0f/120.0f - f * (1.0f/252.0f - f * (1.0f/240.0f - f * (1.0f/132.0f)))));
    float s1 = (1.0f + 0.5f * inv + f * (1.0f/6.0f - f * (1.0f/30.0f - f * (1.0f/42.0f - f * (1.0f/30.0f))))) * inv;
    d0 = r0 + __logf(x) - 0.5f * inv - s0;
    d1 = r1 + s1;
}

// Dual interleaved butterfly reduction (two independent values per step)
__device__ __forceinline__ void wsum2(float& a, float& b)
{
#pragma unroll
    for (int off = 16; off > 0; off >>= 1) {
        float ta = __shfl_xor_sync(0xffffffffu, a, off);
        float tb = __shfl_xor_sync(0xffffffffu, b, off);
        a += ta; b += tb;
    }
}

__device__ __forceinline__ float wsum(float v)
{
#pragma unroll
    for (int off = 16; off > 0; off >>= 1)
        v += __shfl_xor_sync(0xffffffffu, v, off);
    return v;
}

// ---------------------------------------------------------------------------
// Kernel 2: reduce partials (double), then fp32 warp-parallel Newton solve.
// ---------------------------------------------------------------------------
__global__ void finalize_kernel(float* __restrict__ out, int n)
{
    __shared__ double red[8][32];
    __shared__ double stat[32];
    const int t    = threadIdx.x;   // 256 threads
    const int comp = t & 31;
    const int row  = t >> 5;

    double acc = 0.0;
    for (int b = row; b < NBLOCKS; b += 8)
        acc += (double)g_partials[(size_t)b * 32 + comp];
    red[row][comp] = acc;
    __syncthreads();

    if (t < 32) {
        double s = 0.0;
#pragma unroll
        for (int w = 0; w < 8; w++) s += red[w][t];
        stat[t] = s;
    }
    __syncthreads();

    // --- fp32 warp-parallel Newton solve: lane j owns component j ---
    if (t < 32) {
        const double nn_d = (double)n;
        const float  nn   = (float)n;
        const float  rnn  = __fdividef(1.0f, nn);
        const bool   act  = (t < C);

        float m1 = 0.0f, m2 = 0.0f, lp = 0.0f;
        if (act) {
            m1 = (float)(stat[t] / nn_d);
            m2 = (float)(stat[C + t] / nn_d);
            lp = (float)((stat[2*C + t] - stat[30]) / nn_d);  // mean log p_j
        }

        // method-of-moments init
        float ratio = act ? __fdividef(m1 - m2, m2 - m1 * m1) : 0.0f;
        float cc = wsum(ratio) * (1.0f / (float)C);
        float a = act ? (m1 * cc) : 1.0f;           // inactive lanes: safe dummy
        float sumA = wsum(act ? a : 0.0f);

        for (int k = 0; k < 100; k++) {
            // psi/psi' of the scalar sum (lane-uniform) and of own component;
            // the two calls are independent -> ILP hides MUFU latency.
            float dgs, tgs, dga, tga;
            psi01(sumA, dgs, tgs);
            psi01(a,    dga, tga);

            float g = 0.0f, qi = 0.0f, gq = 0.0f;
            if (act) {
                g  = (dgs - dga + lp) * nn;
                qi = __fdividef(-rnn, tga);          // 1/q, q = -n*psi1(a)
                gq = g * qi;
            }
            float num = gq, sumqi = qi;
            wsum2(num, sumqi);

            float den = __fdividef(rnn, tgs) + sumqi;   // 1/z + sum(1/q)
            float b   = __fdividef(num, den);

            float delta = act ? ((g - b) * qi) : 0.0f;  // a_new = a - delta
            a    -= delta;
            sumA -= (num - b * sumqi);                  // sum of deltas, free

            // all |delta| < 1e-4 over C=10 lanes => L1 < 1e-3 (never stops
            // earlier than the reference; extra iterations only refine)
            if (__all_sync(0xffffffffu, fabsf(delta) < 1e-4f)) break;
        }
        if (act) out[t] = a;
    }
}

extern "C" void kernel_launch(void* const* d_in, const int* in_sizes, int n_in,
                              void* d_out, int out_size)
{
    const float* x = (const float*)d_in[0];
    const int n = in_sizes[0] / C;      // number of rows
    float* out = (float*)d_out;

    stats_kernel<<<NBLOCKS, NTHREADS>>>(x, n);
    finalize_kernel<<<1, 256>>>(out, n);
}